// round 3
// baseline (speedup 1.0000x reference)
#include <cuda_runtime.h>

typedef unsigned long long ull;

__device__ __forceinline__ ull pack2(float lo, float hi) {
    ull r; asm("mov.b64 %0, {%1, %2};" : "=l"(r) : "f"(lo), "f"(hi)); return r;
}
__device__ __forceinline__ void unpack2(ull v, float& lo, float& hi) {
    asm("mov.b64 {%0, %1}, %2;" : "=f"(lo), "=f"(hi) : "l"(v));
}
__device__ __forceinline__ void fma2(ull& d, ull a, ull b) {
    asm("fma.rn.f32x2 %0, %1, %2, %0;" : "+l"(d) : "l"(a), "l"(b));
}

#define NB 256
#define LC 400
#define LQ 50
#define DD 128
#define CH 100

// scratch (__device__ globals: allowed; no allocation)
__device__ float d_Sraw[(size_t)NB * LC * LQ];        // 20.5 MB
__device__ float d_cstatP[NB * 4 * LQ * 2];           // partial (m,s)
__device__ float d_cstat[NB * LQ * 2];                // merged (mxc, 1/sum)
__device__ float d_Apart[(size_t)NB * 4 * LQ * DD];   // 26.2 MB

// ---------------- K1: S tile + row softmax (S_bar out) + column partials ----
__global__ __launch_bounds__(256)
void k1_score(const float* __restrict__ g_xc, const float* __restrict__ g_xq,
              const float* __restrict__ g_W0, const float* __restrict__ g_W1,
              const float* __restrict__ g_W2, const int* __restrict__ g_clen,
              const int* __restrict__ g_qlen, float* __restrict__ out)
{
    __shared__ __align__(16) float xqT[32 * 51];
    __shared__ __align__(16) float xcT[32 * 102];
    __shared__ __align__(16) float Ssm[CH * 51];
    __shared__ float sc[CH];
    __shared__ float sq[LQ];

    const int b = blockIdx.y, c0 = blockIdx.x * CH;
    const int t = threadIdx.x, lane = t & 31, w = t >> 5;
    const float* xcb = g_xc + (size_t)b * LC * DD;
    const float* xqb = g_xq + (size_t)b * LQ * DD;

    // s_q[q] = xq[q] . W1
    for (int q = w; q < LQ; q += 8) {
        float4 v = *(const float4*)(xqb + q * DD + lane * 4);
        float4 wv = __ldg((const float4*)g_W1 + lane);
        float p = v.x * wv.x + v.y * wv.y + v.z * wv.z + v.w * wv.w;
        #pragma unroll
        for (int o = 16; o; o >>= 1) p += __shfl_xor_sync(~0u, p, o);
        if (!lane) sq[q] = p;
    }
    if (t < CH) sc[t] = 0.f;

    ull acc[2][5];
    #pragma unroll
    for (int i = 0; i < 2; i++)
        #pragma unroll
        for (int j = 0; j < 5; j++) acc[i][j] = 0ull;
    const int ct = t / 10, qt = t - ct * 10;
    const bool act = t < 250;
    const int cb = ct * 4, qb = qt * 5;

    for (int s4 = 0; s4 < 4; s4++) {
        const int d0 = s4 * 32;
        __syncthreads();
        // stage xqT[dd][q]
        for (int i = t; i < LQ * 32; i += 256) {
            int q = i >> 5;  // lane == dd
            xqT[lane * 51 + q] = xqb[q * DD + d0 + lane];
        }
        // stage xcT[dd][cc] = xc*W2, fold s_c
        float w0v = __ldg(g_W0 + d0 + lane);
        float w2v = __ldg(g_W2 + d0 + lane);
        for (int i = t; i < CH * 32; i += 256) {
            int cc = i >> 5;
            float v = xcb[(size_t)(c0 + cc) * DD + d0 + lane];
            xcT[lane * 102 + cc] = v * w2v;
            float p = v * w0v;
            #pragma unroll
            for (int o = 16; o; o >>= 1) p += __shfl_xor_sync(~0u, p, o);
            if (!lane) sc[cc] += p;
        }
        __syncthreads();
        if (act) {
            #pragma unroll 8
            for (int dd = 0; dd < 32; dd++) {
                ull a0 = *(const ull*)&xcT[dd * 102 + cb];
                ull a1 = *(const ull*)&xcT[dd * 102 + cb + 2];
                #pragma unroll
                for (int j = 0; j < 5; j++) {
                    float xv = xqT[dd * 51 + qb + j];
                    ull bb = pack2(xv, xv);
                    fma2(acc[0][j], a0, bb);
                    fma2(acc[1][j], a1, bb);
                }
            }
        }
    }
    if (act) {
        #pragma unroll
        for (int i = 0; i < 2; i++) {
            #pragma unroll
            for (int j = 0; j < 5; j++) {
                float lo, hi; unpack2(acc[i][j], lo, hi);
                int cA = cb + i * 2, q = qb + j;
                Ssm[cA * 51 + q]       = lo + sc[cA]     + sq[q];
                Ssm[(cA + 1) * 51 + q] = hi + sc[cA + 1] + sq[q];
            }
        }
    }
    __syncthreads();

    // raw S -> scratch
    float* Sraw_b = d_Sraw + ((size_t)b * LC + c0) * LQ;
    for (int i = t; i < CH * LQ; i += 256) {
        int c = i / 50, q = i - c * 50;
        Sraw_b[i] = Ssm[c * 51 + q];
    }
    // row softmax -> S_bar output (q-masked)
    const int qlen = g_qlen[b];
    float* outSB = out + (size_t)NB * LC * 4 * DD;
    for (int r = w; r < CH; r += 8) {
        int q2 = lane + 32;
        float v1 = Ssm[r * 51 + lane];
        float v2 = (q2 < LQ) ? Ssm[r * 51 + q2] : 0.f;
        float m = (lane < qlen) ? v1 : -1e30f;
        if (q2 < LQ && q2 < qlen) m = fmaxf(m, v2);
        #pragma unroll
        for (int o = 16; o; o >>= 1) m = fmaxf(m, __shfl_xor_sync(~0u, m, o));
        float e1 = (lane < qlen) ? __expf(v1 - m) : 0.f;
        float e2 = (q2 < LQ && q2 < qlen) ? __expf(v2 - m) : 0.f;
        float s = e1 + e2;
        #pragma unroll
        for (int o = 16; o; o >>= 1) s += __shfl_xor_sync(~0u, s, o);
        float r1 = 1.f / s;
        float* row = outSB + (size_t)(b * LC + c0 + r) * LQ;
        row[lane] = e1 * r1;
        if (q2 < LQ) row[q2] = e2 * r1;
    }
    // column partial stats (c-masked online softmax)
    const int clen = g_clen[b];
    for (int q = w; q < LQ; q += 8) {
        float m = -1e30f, s = 0.f;
        for (int cc = lane; cc < CH; cc += 32) {
            if (c0 + cc < clen) {
                float v = Ssm[cc * 51 + q];
                if (v > m) { s = s * __expf(m - v) + 1.f; m = v; }
                else       { s += __expf(v - m); }
            }
        }
        #pragma unroll
        for (int o = 16; o; o >>= 1) {
            float m2 = __shfl_xor_sync(~0u, m, o);
            float s2 = __shfl_xor_sync(~0u, s, o);
            if (m2 > m) { s = s * __expf(m - m2) + s2; m = m2; }
            else        { s += s2 * __expf(m2 - m); }
        }
        if (!lane) {
            float* p = d_cstatP + ((size_t)(b * 4 + blockIdx.x) * LQ + q) * 2;
            p[0] = m; p[1] = s;
        }
    }
}

// ---------------- K2: merge column stats ------------------------------------
__global__ __launch_bounds__(64)
void k2_merge()
{
    int b = blockIdx.x, q = threadIdx.x;
    if (q >= LQ) return;
    float m = -1e30f, s = 0.f;
    #pragma unroll
    for (int p = 0; p < 4; p++) {
        const float* pp = d_cstatP + ((size_t)(b * 4 + p) * LQ + q) * 2;
        float mp = pp[0], sp = pp[1];
        if (mp > m) { s = s * __expf(m - mp) + sp; m = mp; }
        else        { s += sp * __expf(mp - m); }
    }
    float* o = d_cstat + ((size_t)b * LQ + q) * 2;
    o[0] = m; o[1] = 1.f / s;
}

// ---------------- K3: S_T output + partial A = S_T @ x_cont -----------------
__global__ __launch_bounds__(256)
void k3_stA(const float* __restrict__ g_xc, const int* __restrict__ g_clen,
            float* __restrict__ out)
{
    __shared__ float stT[CH * 51];
    __shared__ float mx[LQ], inv[LQ];
    const int b = blockIdx.y, chunk = blockIdx.x, c0 = chunk * CH;
    const int t = threadIdx.x, lane = t & 31, w = t >> 5;
    const int clen = g_clen[b];
    if (t < LQ) {
        mx[t]  = d_cstat[((size_t)b * LQ + t) * 2];
        inv[t] = d_cstat[((size_t)b * LQ + t) * 2 + 1];
    }
    __syncthreads();
    const float* Sraw_b = d_Sraw + ((size_t)b * LC + c0) * LQ;
    for (int i = t; i < CH * LQ; i += 256) {
        int cc = i / 50, q = i - cc * 50;
        float v = 0.f;
        if (c0 + cc < clen) v = __expf(Sraw_b[i] - mx[q]) * inv[q];
        stT[cc * 51 + q] = v;
    }
    __syncthreads();
    // S_T output, q-major coalesced
    float* outST = out + (size_t)NB * LC * 4 * DD + (size_t)NB * LC * LQ;
    float* ST_b = outST + (size_t)b * LQ * LC + c0;
    for (int i = t; i < CH * LQ; i += 256) {
        int q = i / 100, cc = i - q * 100;
        ST_b[(size_t)q * LC + cc] = stT[cc * 51 + q];
    }
    // partial A[q][d] += st[cc][q] * xc[c0+cc][d]
    const float* xcc = g_xc + ((size_t)b * LC + c0) * DD;
    const int nq = (w < 2) ? 7 : 6;   // q = w + 8j covers 0..49
    ull accA[7][2];
    #pragma unroll
    for (int j = 0; j < 7; j++) { accA[j][0] = 0ull; accA[j][1] = 0ull; }
    #pragma unroll 2
    for (int cc = 0; cc < CH; cc++) {
        union { float4 f; ull u[2]; } X;
        X.f = *(const float4*)(xcc + (size_t)cc * DD + lane * 4);
        #pragma unroll
        for (int j = 0; j < 7; j++) {
            if (j < nq) {
                float sv = stT[cc * 51 + w + 8 * j];
                ull sb = pack2(sv, sv);
                fma2(accA[j][0], X.u[0], sb);
                fma2(accA[j][1], X.u[1], sb);
            }
        }
    }
    float* Ap = d_Apart + (size_t)(b * 4 + chunk) * LQ * DD;
    #pragma unroll
    for (int j = 0; j < 7; j++) {
        if (j < nq) {
            int q = w + 8 * j;
            union { float4 f; ull u[2]; } R;
            R.u[0] = accA[j][0]; R.u[1] = accA[j][1];
            *(float4*)(Ap + (size_t)q * DD + lane * 4) = R.f;
        }
    }
}

// ---------------- K4: c2q, q2c, fused concat --------------------------------
__global__ __launch_bounds__(256)
void k4_final(const float* __restrict__ g_xc, const float* __restrict__ g_xq,
              float* __restrict__ out)
{
    extern __shared__ float sm4[];
    float* xqs = sm4;            // 50*132 = 6600
    float* As  = sm4 + 6600;     // 6600
    float* SB  = sm4 + 13200;    // 100*51 = 5100  (total 18300 fl = 73.2KB)
    const int b = blockIdx.y, c0 = blockIdx.x * CH;
    const int t = threadIdx.x, lane = t & 31, w = t >> 5;
    const float* xqb = g_xq + (size_t)b * LQ * DD;
    const float* xcb = g_xc + (size_t)b * LC * DD;
    float* outSB = out + (size_t)NB * LC * 4 * DD;

    for (int i = t; i < LQ * DD; i += 256) {
        int q = i >> 7, d = i & 127;
        xqs[q * 132 + d] = xqb[i];
        float s = 0.f;
        #pragma unroll
        for (int p = 0; p < 4; p++)
            s += d_Apart[(size_t)(b * 4 + p) * LQ * DD + (size_t)q * DD + d];
        As[q * 132 + d] = s;
    }
    const float* SBg = outSB + ((size_t)b * LC + c0) * LQ;
    for (int i = t; i < CH * LQ; i += 256) {
        int cc = i / 50, q = i - cc * 50;
        SB[cc * 51 + q] = SBg[i];
    }
    __syncthreads();

    #pragma unroll 1
    for (int half = 0; half < 2; half++) {
        const int nk = (w < 2) ? 7 : 6;  // cc = half*50 + w + 8k covers chunk
        ull a1[7][2], a2[7][2];
        #pragma unroll
        for (int k = 0; k < 7; k++) {
            a1[k][0] = a1[k][1] = 0ull;
            a2[k][0] = a2[k][1] = 0ull;
        }
        const int cbase = half * 50 + w;
        #pragma unroll 2
        for (int q = 0; q < LQ; q++) {
            union { float4 f; ull u[2]; } XQ, AV;
            XQ.f = *(const float4*)&xqs[q * 132 + lane * 4];
            AV.f = *(const float4*)&As[q * 132 + lane * 4];
            #pragma unroll
            for (int k = 0; k < 7; k++) {
                if (k < nk) {
                    float sv = SB[(cbase + 8 * k) * 51 + q];
                    ull sb = pack2(sv, sv);
                    fma2(a1[k][0], XQ.u[0], sb);
                    fma2(a1[k][1], XQ.u[1], sb);
                    fma2(a2[k][0], AV.u[0], sb);
                    fma2(a2[k][1], AV.u[1], sb);
                }
            }
        }
        #pragma unroll
        for (int k = 0; k < 7; k++) {
            if (k < nk) {
                int c = c0 + cbase + 8 * k;
                float4 xcv = *(const float4*)(xcb + (size_t)c * DD + lane * 4);
                union { float4 f; ull u[2]; } C2Q, Q2C;
                C2Q.u[0] = a1[k][0]; C2Q.u[1] = a1[k][1];
                Q2C.u[0] = a2[k][0]; Q2C.u[1] = a2[k][1];
                float* base = out + ((size_t)b * LC + c) * (4 * DD) + lane * 4;
                *(float4*)(base)        = xcv;
                *(float4*)(base + 128)  = C2Q.f;
                *(float4*)(base + 256)  = make_float4(xcv.x * C2Q.f.x, xcv.y * C2Q.f.y,
                                                      xcv.z * C2Q.f.z, xcv.w * C2Q.f.w);
                *(float4*)(base + 384)  = make_float4(xcv.x * Q2C.f.x, xcv.y * Q2C.f.y,
                                                      xcv.z * Q2C.f.z, xcv.w * Q2C.f.w);
            }
        }
    }
}

extern "C" void kernel_launch(void* const* d_in, const int* in_sizes, int n_in,
                              void* d_out, int out_size)
{
    const float* xc  = (const float*)d_in[0];
    const float* xq  = (const float*)d_in[1];
    const float* W0  = (const float*)d_in[2];
    const float* W1  = (const float*)d_in[3];
    const float* W2  = (const float*)d_in[4];
    const int* clen  = (const int*)d_in[5];
    const int* qlen  = (const int*)d_in[6];
    float* out = (float*)d_out;

    cudaFuncSetAttribute(k4_final, cudaFuncAttributeMaxDynamicSharedMemorySize,
                         18300 * (int)sizeof(float));

    dim3 g(4, NB);
    k1_score<<<g, 256>>>(xc, xq, W0, W1, W2, clen, qlen, out);
    k2_merge<<<NB, 64>>>();
    k3_stA<<<g, 256>>>(xc, clen, out);
    k4_final<<<g, 256, 18300 * sizeof(float)>>>(xc, xq, out);
}